// round 7
// baseline (speedup 1.0000x reference)
#include <cuda_runtime.h>
#include <cuda_bf16.h>
#include <math.h>

typedef unsigned int u32;

#define BB   256
#define TT   512
#define HH   256
#define LL   4
#define NBLK 128
#define NTHR 256
#define GRP  16          // blocks per barrier group (same bt)

#define AS   132         // A row stride (words): 128 k2 + 4 pad
#define BSB  132         // B row stride (words): 128 k2 + 4 pad
#define GS   33          // gate smem row stride

#define SZ_A (64 * AS)   // 8448 words
#define SZ_B (32 * BSB)  // 4224 words
#define SZ_G (64 * GS)   // 2112 words

#define OFF_AHH_HI 0
#define OFF_AHH_LO (SZ_A)
#define OFF_AIH_HI (2 * SZ_A)
#define OFF_AIH_LO (3 * SZ_A)
#define OFF_B_HI   (4 * SZ_A)
#define OFF_B_LO   (4 * SZ_A + SZ_B)
#define OFF_G      (4 * SZ_A + 2 * SZ_B)
#define OFF_BSN    (OFF_G + SZ_G)
#define OFF_BS0    (OFF_BSN + 64)
#define OFF_WXS    (OFF_BS0 + 64)
#define OFF_XS     (OFF_WXS + 64)
#define SMEM_WORDS (OFF_XS + 32)
#define SMEM_BYTES (SMEM_WORDS * 4)   // ~178.3 KB

// ---------------- device scratch ----------------
__device__ __align__(128) u32 g_hAhi[(size_t)TT * BB * 128];
__device__ __align__(128) u32 g_hAlo[(size_t)TT * BB * 128];
__device__ __align__(128) u32 g_hBhi[(size_t)TT * BB * 128];
__device__ __align__(128) u32 g_hBlo[(size_t)TT * BB * 128];
__device__ __align__(128) float g_gih[(size_t)NBLK * TT * 2048];
__device__ unsigned g_bar[8 * LL * TT];
__device__ unsigned g_fin;

struct Params {
    const float* x;
    const float* Wih[LL];
    const float* Whh[LL];
    const float* bih[LL];
    const float* bhh[LL];
    const float* fcW;
    const float* fcb;
    float* out;
};

// ---------------- helpers ----------------
__device__ __forceinline__ float sigf(float v) {
    return __fdividef(1.0f, 1.0f + __expf(-v));
}
__device__ __forceinline__ float tanhfast(float v) {
    return 1.0f - __fdividef(2.0f, __expf(2.0f * v) + 1.0f);
}

__device__ __forceinline__ void split_pack(float x, float y, u32& hi, u32& lo) {
    __nv_bfloat162 h2, l2;
    h2.x = __float2bfloat16_rn(x);
    h2.y = __float2bfloat16_rn(y);
    l2.x = __float2bfloat16_rn(x - __bfloat162float(h2.x));
    l2.y = __float2bfloat16_rn(y - __bfloat162float(h2.y));
    hi = *reinterpret_cast<u32*>(&h2);
    lo = *reinterpret_cast<u32*>(&l2);
}

__device__ __forceinline__ void mma16816(float c[4], u32 a0, u32 a1, u32 a2, u32 a3,
                                         u32 b0, u32 b1) {
    asm("mma.sync.aligned.m16n8k16.row.col.f32.bf16.bf16.f32 "
        "{%0,%1,%2,%3}, {%4,%5,%6,%7}, {%8,%9}, {%0,%1,%2,%3};"
        : "+f"(c[0]), "+f"(c[1]), "+f"(c[2]), "+f"(c[3])
        : "r"(a0), "r"(a1), "r"(a2), "r"(a3), "r"(b0), "r"(b1));
}

__device__ __forceinline__ void ldsm4(u32& r0, u32& r1, u32& r2, u32& r3, u32 addr) {
    asm volatile("ldmatrix.sync.aligned.m8n8.x4.shared.b16 {%0,%1,%2,%3}, [%4];"
                 : "=r"(r0), "=r"(r1), "=r"(r2), "=r"(r3) : "r"(addr));
}

// smem-A 3-pass mma (used only for the per-layer tail ih projection)
__device__ __forceinline__ void mma_full_smem(u32 aHi, u32 aLo, u32 bHiA, u32 bLoA,
                                              float c[2][4]) {
    #pragma unroll
    for (int kk = 0; kk < 16; ++kk) {
        u32 a0, a1, a2, a3, l0, l1, l2, l3;
        u32 b0, b1, b2, b3, m0, m1, m2, m3;
        ldsm4(a0, a1, a2, a3, aHi + kk * 32);
        ldsm4(l0, l1, l2, l3, aLo + kk * 32);
        ldsm4(b0, b1, b2, b3, bHiA + kk * 32);
        ldsm4(m0, m1, m2, m3, bLoA + kk * 32);
        mma16816(c[0], a0, a1, a2, a3, b0, b2);
        mma16816(c[1], a0, a1, a2, a3, b1, b3);
        mma16816(c[0], a0, a1, a2, a3, m0, m2);
        mma16816(c[1], a0, a1, a2, a3, m1, m3);
        mma16816(c[0], l0, l1, l2, l3, b0, b2);
        mma16816(c[1], l0, l1, l2, l3, b1, b3);
    }
}

// hardened barrier: release-arrive via red.global, acquire-poll + nanosleep backoff
__device__ __forceinline__ void bar_arrive(unsigned* p) {
    __syncthreads();
    if (threadIdx.x == 0) {
        asm volatile("red.release.gpu.global.add.u32 [%0], %1;"
                     :: "l"(p), "r"(1u) : "memory");
    }
}
__device__ __forceinline__ void bar_wait(unsigned* p, unsigned target) {
    if (threadIdx.x == 0) {
        unsigned v;
        asm volatile("ld.acquire.gpu.global.u32 %0, [%1];" : "=r"(v) : "l"(p) : "memory");
        while (v < target) {
            __nanosleep(32);
            asm volatile("ld.acquire.gpu.global.u32 %0, [%1];" : "=r"(v) : "l"(p) : "memory");
        }
    }
    __syncthreads();
}

__device__ __forceinline__ void load_W(const float* __restrict__ W, int j0,
                                       u32* __restrict__ shi, u32* __restrict__ slo) {
    for (int i = threadIdx.x; i < 64 * 128; i += NTHR) {
        const int m = i >> 7;
        const int k2 = i & 127;
        const int row = (m >> 4) * HH + j0 + (m & 15);
        const float2 w = *(const float2*)(W + (size_t)row * HH + 2 * k2);
        split_pack(w.x, w.y, shi[m * AS + k2], slo[m * AS + k2]);
    }
}

__device__ __forceinline__ void load_B(const u32* __restrict__ ghi, const u32* __restrict__ glo,
                                       int t, int b0, u32* __restrict__ sBhi,
                                       u32* __restrict__ sBlo, int wid, int lane) {
    #pragma unroll
    for (int r = 0; r < 4; ++r) {
        const int bbr = 4 * wid + r;
        const size_t gi = ((size_t)t * BB + b0 + bbr) * 128 + lane * 4;
        const uint4 vh = *(const uint4*)(ghi + gi);
        const uint4 vl = *(const uint4*)(glo + gi);
        *(uint4*)(sBhi + bbr * BSB + lane * 4) = vh;
        *(uint4*)(sBlo + bbr * BSB + lane * 4) = vl;
    }
}

// ---------------- kernel ----------------
__global__ void __launch_bounds__(NTHR, 1) lstm_fused(Params p) {
    extern __shared__ u32 sm[];
    u32* sAhhHi = sm + OFF_AHH_HI;
    u32* sAhhLo = sm + OFF_AHH_LO;
    u32* sAihHi = sm + OFF_AIH_HI;
    u32* sAihLo = sm + OFF_AIH_LO;
    u32* sBhi   = sm + OFF_B_HI;
    u32* sBlo   = sm + OFF_B_LO;
    float* gsm  = (float*)(sm + OFF_G);
    float* bsn  = (float*)(sm + OFF_BSN);
    float* bs0  = (float*)(sm + OFF_BS0);
    float* wxs  = (float*)(sm + OFF_WXS);
    float* xs   = (float*)(sm + OFF_XS);

    const int tid  = threadIdx.x;
    const int bid  = blockIdx.x;
    const int jt   = bid >> 3;
    const int bt   = bid & 7;
    const int j0   = jt * 16;
    const int b0   = bt * 32;
    const int wid  = tid >> 5;
    const int lane = tid & 31;
    const int lr   = lane >> 2;
    const int lc   = lane & 3;
    const int mb   = (wid >> 1) * 16;
    const int wn   = wid & 1;
    const int jp   = tid & 7;
    const int bbx  = tid >> 3;

    const u32 aoffw = (u32)((mb + ((lane >> 3) & 1) * 8 + (lane & 7)) * AS + (lane >> 4) * 4);
    const u32 boffw = (u32)((wn * 16 + ((lane >> 3) & 1) * 8 + (lane & 7)) * BSB + (lane >> 4) * 4);
    const u32 smbase = (u32)__cvta_generic_to_shared(sm);
    const u32 aHH_hi = smbase + (OFF_AHH_HI + aoffw) * 4;
    const u32 aHH_lo = smbase + (OFF_AHH_LO + aoffw) * 4;
    const u32 aIH_hi = smbase + (OFF_AIH_HI + aoffw) * 4;
    const u32 aIH_lo = smbase + (OFF_AIH_LO + aoffw) * 4;
    const u32 bAd_hi = smbase + (OFF_B_HI + boffw) * 4;
    const u32 bAd_lo = smbase + (OFF_B_LO + boffw) * 4;

    float* gG0 = g_gih + (size_t)bid * TT * 2048;
    unsigned* bars = g_bar + bt * (LL * TT);
    const int col0 = wn * 16 + 2 * lc;

    // persistent Whh fragments (reloaded once per layer)
    u32 Ah[16][4], Al[16][4];

    // initial staging: layer-0 Whh, layer-1 Wih, biases
    load_W(p.Whh[0], j0, sAhhHi, sAhhLo);
    load_W(p.Wih[1], j0, sAihHi, sAihLo);
    if (tid < 64) {
        const int row = (tid >> 4) * HH + j0 + (tid & 15);
        bs0[tid] = p.bih[0][row] + p.bhh[0][row];
        wxs[tid] = p.Wih[0][row];             // W_ih0 is [4H, 1]
        bsn[tid] = p.bih[1][row] + p.bhh[1][row];
    }
    __syncthreads();
    #pragma unroll
    for (int kk = 0; kk < 16; ++kk) {
        ldsm4(Ah[kk][0], Ah[kk][1], Ah[kk][2], Ah[kk][3], aHH_hi + kk * 32);
        ldsm4(Al[kk][0], Al[kk][1], Al[kk][2], Al[kk][3], aHH_lo + kk * 32);
    }

    for (int l = 0; l < LL; ++l) {
        u32* outhi = (l & 1) ? g_hBhi : g_hAhi;
        u32* outlo = (l & 1) ? g_hBlo : g_hAlo;
        float cc0 = 0.f, cc1 = 0.f;
        const bool do_ih = (l < 3);

        for (int t = 0; t < TT; ++t) {
            float c[2][4];
            if (l > 0) {
                const float* gw = gG0 + (size_t)t * 2048;
                const float2 v00 = *(const float2*)(gw + (mb + lr) * 32 + col0);
                const float2 v10 = *(const float2*)(gw + (mb + 8 + lr) * 32 + col0);
                const float2 v01 = *(const float2*)(gw + (mb + lr) * 32 + col0 + 8);
                const float2 v11 = *(const float2*)(gw + (mb + 8 + lr) * 32 + col0 + 8);
                c[0][0] = v00.x; c[0][1] = v00.y; c[0][2] = v10.x; c[0][3] = v10.y;
                c[1][0] = v01.x; c[1][1] = v01.y; c[1][2] = v11.x; c[1][3] = v11.y;
            } else {
                if (tid < 32) xs[tid] = p.x[(size_t)(b0 + tid) * TT + t];
            }

            if (t > 0) bar_wait(&bars[l * TT + t - 1], GRP);
            else       __syncthreads();

            if (t > 0) {
                load_B(outhi, outlo, t - 1, b0, sBhi, sBlo, wid, lane);
                __syncthreads();
            }

            if (l == 0) {
                const float w0 = wxs[mb + lr],     bv0 = bs0[mb + lr];
                const float w1 = wxs[mb + 8 + lr], bv1 = bs0[mb + 8 + lr];
                const float x00 = xs[col0], x01 = xs[col0 + 1];
                const float x10 = xs[col0 + 8], x11 = xs[col0 + 9];
                c[0][0] = fmaf(w0, x00, bv0); c[0][1] = fmaf(w0, x01, bv0);
                c[0][2] = fmaf(w1, x00, bv1); c[0][3] = fmaf(w1, x01, bv1);
                c[1][0] = fmaf(w0, x10, bv0); c[1][1] = fmaf(w0, x11, bv0);
                c[1][2] = fmaf(w1, x10, bv1); c[1][3] = fmaf(w1, x11, bv1);
            }

            // fused MMA: hh (A in regs) + ih (A from smem), sharing B fragments
            if (t > 0) {
                if (do_ih) {
                    float c2[2][4];
                    const float bn0 = bsn[mb + lr], bn1 = bsn[mb + 8 + lr];
                    c2[0][0] = bn0; c2[0][1] = bn0; c2[0][2] = bn1; c2[0][3] = bn1;
                    c2[1][0] = bn0; c2[1][1] = bn0; c2[1][2] = bn1; c2[1][3] = bn1;
                    #pragma unroll
                    for (int kk = 0; kk < 16; ++kk) {
                        u32 b0r, b1r, b2r, b3r, m0, m1, m2, m3;
                        u32 p0, p1, p2, p3, q0, q1, q2, q3;
                        ldsm4(b0r, b1r, b2r, b3r, bAd_hi + kk * 32);
                        ldsm4(m0, m1, m2, m3, bAd_lo + kk * 32);
                        ldsm4(p0, p1, p2, p3, aIH_hi + kk * 32);
                        ldsm4(q0, q1, q2, q3, aIH_lo + kk * 32);
                        // interleave accumulator groups for ILP
                        mma16816(c[0],  Ah[kk][0], Ah[kk][1], Ah[kk][2], Ah[kk][3], b0r, b2r);
                        mma16816(c[1],  Ah[kk][0], Ah[kk][1], Ah[kk][2], Ah[kk][3], b1r, b3r);
                        mma16816(c2[0], p0, p1, p2, p3, b0r, b2r);
                        mma16816(c2[1], p0, p1, p2, p3, b1r, b3r);
                        mma16816(c[0],  Ah[kk][0], Ah[kk][1], Ah[kk][2], Ah[kk][3], m0, m2);
                        mma16816(c[1],  Ah[kk][0], Ah[kk][1], Ah[kk][2], Ah[kk][3], m1, m3);
                        mma16816(c2[0], p0, p1, p2, p3, m0, m2);
                        mma16816(c2[1], p0, p1, p2, p3, m1, m3);
                        mma16816(c[0],  Al[kk][0], Al[kk][1], Al[kk][2], Al[kk][3], b0r, b2r);
                        mma16816(c[1],  Al[kk][0], Al[kk][1], Al[kk][2], Al[kk][3], b1r, b3r);
                        mma16816(c2[0], q0, q1, q2, q3, b0r, b2r);
                        mma16816(c2[1], q0, q1, q2, q3, b1r, b3r);
                    }
                    // write ih projection for layer l+1, timestep t-1
                    float* gw = gG0 + (size_t)(t - 1) * 2048;
                    *(float2*)(gw + (mb + lr) * 32 + col0)         = make_float2(c2[0][0], c2[0][1]);
                    *(float2*)(gw + (mb + 8 + lr) * 32 + col0)     = make_float2(c2[0][2], c2[0][3]);
                    *(float2*)(gw + (mb + lr) * 32 + col0 + 8)     = make_float2(c2[1][0], c2[1][1]);
                    *(float2*)(gw + (mb + 8 + lr) * 32 + col0 + 8) = make_float2(c2[1][2], c2[1][3]);
                } else {
                    #pragma unroll
                    for (int kk = 0; kk < 16; ++kk) {
                        u32 b0r, b1r, b2r, b3r, m0, m1, m2, m3;
                        ldsm4(b0r, b1r, b2r, b3r, bAd_hi + kk * 32);
                        ldsm4(m0, m1, m2, m3, bAd_lo + kk * 32);
                        mma16816(c[0], Ah[kk][0], Ah[kk][1], Ah[kk][2], Ah[kk][3], b0r, b2r);
                        mma16816(c[1], Ah[kk][0], Ah[kk][1], Ah[kk][2], Ah[kk][3], b1r, b3r);
                        mma16816(c[0], Ah[kk][0], Ah[kk][1], Ah[kk][2], Ah[kk][3], m0, m2);
                        mma16816(c[1], Ah[kk][0], Ah[kk][1], Ah[kk][2], Ah[kk][3], m1, m3);
                        mma16816(c[0], Al[kk][0], Al[kk][1], Al[kk][2], Al[kk][3], b0r, b2r);
                        mma16816(c[1], Al[kk][0], Al[kk][1], Al[kk][2], Al[kk][3], b1r, b3r);
                    }
                }
            }

            // gates -> smem
            gsm[(mb + lr) * GS + col0]         = c[0][0];
            gsm[(mb + lr) * GS + col0 + 1]     = c[0][1];
            gsm[(mb + 8 + lr) * GS + col0]     = c[0][2];
            gsm[(mb + 8 + lr) * GS + col0 + 1] = c[0][3];
            gsm[(mb + lr) * GS + col0 + 8]     = c[1][0];
            gsm[(mb + lr) * GS + col0 + 9]     = c[1][1];
            gsm[(mb + 8 + lr) * GS + col0 + 8] = c[1][2];
            gsm[(mb + 8 + lr) * GS + col0 + 9] = c[1][3];
            __syncthreads();

            // elementwise LSTM cell
            {
                const int jl0 = 2 * jp, jl1 = jl0 + 1;
                const float ig0 = gsm[jl0 * GS + bbx];
                const float fg0 = gsm[(16 + jl0) * GS + bbx];
                const float gg0 = gsm[(32 + jl0) * GS + bbx];
                const float og0 = gsm[(48 + jl0) * GS + bbx];
                const float ig1 = gsm[jl1 * GS + bbx];
                const float fg1 = gsm[(16 + jl1) * GS + bbx];
                const float gg1 = gsm[(32 + jl1) * GS + bbx];
                const float og1 = gsm[(48 + jl1) * GS + bbx];

                cc0 = sigf(fg0) * cc0 + sigf(ig0) * tanhfast(gg0);
                cc1 = sigf(fg1) * cc1 + sigf(ig1) * tanhfast(gg1);
                const float h0 = sigf(og0) * tanhfast(cc0);
                const float h1 = sigf(og1) * tanhfast(cc1);

                u32 hiw, low;
                split_pack(h0, h1, hiw, low);
                const size_t wi = ((size_t)t * BB + b0 + bbx) * 128 + (j0 >> 1) + jp;
                outhi[wi] = hiw;
                outlo[wi] = low;
            }

            bar_arrive(&bars[l * TT + t]);
        }

        if (l < 3) {
            // produce gih_{l+1}[T-1] from h_l(T-1) (smem-A path, off steady-state)
            bar_wait(&bars[l * TT + TT - 1], GRP);
            load_B(outhi, outlo, TT - 1, b0, sBhi, sBlo, wid, lane);
            __syncthreads();
            {
                float c2[2][4];
                const float bn0 = bsn[mb + lr], bn1 = bsn[mb + 8 + lr];
                c2[0][0] = bn0; c2[0][1] = bn0; c2[0][2] = bn1; c2[0][3] = bn1;
                c2[1][0] = bn0; c2[1][1] = bn0; c2[1][2] = bn1; c2[1][3] = bn1;
                mma_full_smem(aIH_hi, aIH_lo, bAd_hi, bAd_lo, c2);
                float* gw = gG0 + (size_t)(TT - 1) * 2048;
                *(float2*)(gw + (mb + lr) * 32 + col0)         = make_float2(c2[0][0], c2[0][1]);
                *(float2*)(gw + (mb + 8 + lr) * 32 + col0)     = make_float2(c2[0][2], c2[0][3]);
                *(float2*)(gw + (mb + lr) * 32 + col0 + 8)     = make_float2(c2[1][0], c2[1][1]);
                *(float2*)(gw + (mb + 8 + lr) * 32 + col0 + 8) = make_float2(c2[1][2], c2[1][3]);
            }
            __syncthreads();
            // stage next layer weights
            load_W(p.Whh[l + 1], j0, sAhhHi, sAhhLo);
            if (l + 2 < LL) {
                load_W(p.Wih[l + 2], j0, sAihHi, sAihLo);
                if (tid < 64) {
                    const int row = (tid >> 4) * HH + j0 + (tid & 15);
                    bsn[tid] = p.bih[l + 2][row] + p.bhh[l + 2][row];
                }
            }
            __syncthreads();
            // reload persistent Whh fragments for the next layer
            #pragma unroll
            for (int kk = 0; kk < 16; ++kk) {
                ldsm4(Ah[kk][0], Ah[kk][1], Ah[kk][2], Ah[kk][3], aHH_hi + kk * 32);
                ldsm4(Al[kk][0], Al[kk][1], Al[kk][2], Al[kk][3], aHH_lo + kk * 32);
            }
        }
    }

    // signal completion
    __syncthreads();
    if (tid == 0) {
        asm volatile("red.release.gpu.global.add.u32 [%0], %1;"
                     :: "l"(&g_fin), "r"(1u) : "memory");
    }

    // block 0: wait for everyone, FC on h_3(T-1), reset barrier state
    if (bid == 0) {
        if (tid == 0) {
            unsigned v;
            asm volatile("ld.acquire.gpu.global.u32 %0, [%1];" : "=r"(v) : "l"(&g_fin) : "memory");
            while (v < (unsigned)NBLK) {
                __nanosleep(64);
                asm volatile("ld.acquire.gpu.global.u32 %0, [%1];" : "=r"(v) : "l"(&g_fin) : "memory");
            }
        }
        __syncthreads();

        const int b = tid;
        float acc = p.fcb[0];
        const u32* bh = g_hBhi + ((size_t)(TT - 1) * BB + b) * 128;
        const u32* bl = g_hBlo + ((size_t)(TT - 1) * BB + b) * 128;
        #pragma unroll 4
        for (int k2 = 0; k2 < 128; ++k2) {
            const u32 hw = bh[k2];
            const u32 lw = bl[k2];
            const __nv_bfloat162 h2 = *reinterpret_cast<const __nv_bfloat162*>(&hw);
            const __nv_bfloat162 l2 = *reinterpret_cast<const __nv_bfloat162*>(&lw);
            const float h0 = __bfloat162float(h2.x) + __bfloat162float(l2.x);
            const float h1 = __bfloat162float(h2.y) + __bfloat162float(l2.y);
            const float2 w = *(const float2*)(p.fcW + 2 * k2);
            acc = fmaf(w.x, h0, fmaf(w.y, h1, acc));
        }
        p.out[b] = acc;

        for (int i = tid; i < 8 * LL * TT; i += NTHR) g_bar[i] = 0;
        if (tid == 0) g_fin = 0;
        __threadfence();
    }
}

extern "C" void kernel_launch(void* const* d_in, const int* in_sizes, int n_in,
                              void* d_out, int out_size) {
    (void)in_sizes; (void)n_in; (void)out_size;
    Params p;
    p.x = (const float*)d_in[0];
    for (int l = 0; l < LL; ++l) {
        p.Wih[l] = (const float*)d_in[1 + 4 * l];
        p.Whh[l] = (const float*)d_in[2 + 4 * l];
        p.bih[l] = (const float*)d_in[3 + 4 * l];
        p.bhh[l] = (const float*)d_in[4 + 4 * l];
    }
    p.fcW = (const float*)d_in[17];
    p.fcb = (const float*)d_in[18];
    p.out = (float*)d_out;

    cudaFuncSetAttribute(lstm_fused, cudaFuncAttributeMaxDynamicSharedMemorySize, SMEM_BYTES);
    lstm_fused<<<NBLK, NTHR, SMEM_BYTES>>>(p);
}